// round 6
// baseline (speedup 1.0000x reference)
#include <cuda_runtime.h>

#define N_NODES 200000
#define E_TP    200000
#define E_IT    3200000
#define NB      ((N_NODES + 1023) / 1024)   // 196 scan blocks
#define CONV_GRID 296                        // persistent: 2 blocks/SM * 148

// -------- scratch (static device globals; no allocation) --------
__device__ int   g_cnt_tp[N_NODES];
__device__ int   g_cnt_it[N_NODES];
__device__ int   g_off_tp[N_NODES + 1];
__device__ int   g_off_it[N_NODES + 1];
__device__ int   g_src_tp[E_TP];
__device__ int   g_src_it[E_IT];
__device__ int   g_bsum[2 * 256];
__device__ float g_h0[N_NODES * 32];
__device__ float g_h1[N_NODES * 32];

// -------- CSR build --------
// counts start at 0: zero-initialized at load; re-zeroed by conv0 each replay.
__global__ void hist_kernel(const int* __restrict__ ei_tp,
                            const int* __restrict__ ei_it) {
    int e = blockIdx.x * blockDim.x + threadIdx.x;
    if (e < E_TP) atomicAdd(&g_cnt_tp[ei_tp[E_TP + e]], 1);
    if (e < E_IT) atomicAdd(&g_cnt_it[ei_it[E_IT + e]], 1);
}

// pass 1: per-block sums (1024 elems/block) for both count arrays
__global__ void __launch_bounds__(1024) scan1_kernel() {
    int b = blockIdx.x, t = threadIdx.x;
    int i = b * 1024 + t;
    int vtp = (i < N_NODES) ? g_cnt_tp[i] : 0;
    int vit = (i < N_NODES) ? g_cnt_it[i] : 0;
#pragma unroll
    for (int o = 16; o; o >>= 1) {
        vtp += __shfl_down_sync(0xffffffffu, vtp, o);
        vit += __shfl_down_sync(0xffffffffu, vit, o);
    }
    __shared__ int stp[32], sit[32];
    if ((t & 31) == 0) { stp[t >> 5] = vtp; sit[t >> 5] = vit; }
    __syncthreads();
    if (t < 32) {
        int a = stp[t], c = sit[t];
#pragma unroll
        for (int o = 16; o; o >>= 1) {
            a += __shfl_down_sync(0xffffffffu, a, o);
            c += __shfl_down_sync(0xffffffffu, c, o);
        }
        if (t == 0) { g_bsum[b] = a; g_bsum[256 + b] = c; }
    }
}

// pass 2+3 fused: each block computes its own prefix over block sums (parallel
// reduction), then does the block-local exclusive scan for both arrays.
// Also resets g_cnt_* to 0 so scatter can use them as cursors.
__global__ void __launch_bounds__(1024) scan23_kernel() {
    __shared__ int s[1024];
    __shared__ int red0[32], red1[32];
    __shared__ int s_boff[2];
    int b = blockIdx.x, t = threadIdx.x;

    // prefix of block sums: sum of g_bsum[t'] for t' < b  (b < NB <= 1024)
    int p0 = (t < b) ? g_bsum[t] : 0;
    int p1 = (t < b) ? g_bsum[256 + t] : 0;
#pragma unroll
    for (int o = 16; o; o >>= 1) {
        p0 += __shfl_down_sync(0xffffffffu, p0, o);
        p1 += __shfl_down_sync(0xffffffffu, p1, o);
    }
    if ((t & 31) == 0) { red0[t >> 5] = p0; red1[t >> 5] = p1; }
    __syncthreads();
    if (t < 32) {
        int a = red0[t], c = red1[t];
#pragma unroll
        for (int o = 16; o; o >>= 1) {
            a += __shfl_down_sync(0xffffffffu, a, o);
            c += __shfl_down_sync(0xffffffffu, c, o);
        }
        if (t == 0) { s_boff[0] = a; s_boff[1] = c; }
    }
    __syncthreads();
    int boff0 = s_boff[0], boff1 = s_boff[1];

    int i = b * 1024 + t;

    // temp_previous
    int v = (i < N_NODES) ? g_cnt_tp[i] : 0;
    if (i < N_NODES) g_cnt_tp[i] = 0;   // reset cursor for scatter
    s[t] = v;
    __syncthreads();
    for (int d = 1; d < 1024; d <<= 1) {
        int w = (t >= d) ? s[t - d] : 0;
        __syncthreads();
        s[t] += w;
        __syncthreads();
    }
    if (i < N_NODES) g_off_tp[i] = boff0 + s[t] - v;
    __syncthreads();

    // intersects
    v = (i < N_NODES) ? g_cnt_it[i] : 0;
    if (i < N_NODES) g_cnt_it[i] = 0;   // reset cursor for scatter
    s[t] = v;
    __syncthreads();
    for (int d = 1; d < 1024; d <<= 1) {
        int w = (t >= d) ? s[t - d] : 0;
        __syncthreads();
        s[t] += w;
        __syncthreads();
    }
    if (i < N_NODES) g_off_it[i] = boff1 + s[t] - v;

    if (b == 0 && t == 0) { g_off_tp[N_NODES] = E_TP; g_off_it[N_NODES] = E_IT; }
}

__global__ void scatter_kernel(const int* __restrict__ ei_tp,
                               const int* __restrict__ ei_it) {
    int e = blockIdx.x * blockDim.x + threadIdx.x;
    if (e < E_TP) {
        int src = ei_tp[e];
        int dst = ei_tp[E_TP + e];
        int pos = g_off_tp[dst] + atomicAdd(&g_cnt_tp[dst], 1);
        g_src_tp[pos] = src;
    }
    if (e < E_IT) {
        int src = ei_it[e];
        int dst = ei_it[E_IT + e];
        int pos = g_off_it[dst] + atomicAdd(&g_cnt_it[dst], 1);
        g_src_it[pos] = src;
    }
}

// -------- fused hetero-conv layer (persistent) --------
// One warp per node per iteration; lane = out-channel. Weights live in
// registers (96 regs), A/M/X transposed via smem float4 broadcast.
// IO: 0 = xin->g_h0, 1 = g_h0->g_h1, 2 = g_h1->g_h0.
// ZERO: also reset g_cnt_* (for the NEXT graph replay's hist_kernel).
template <int CIN, bool RES, int IO, bool ZERO>
__global__ void __launch_bounds__(256, 2)
conv_kernel(const float* __restrict__ xin,
            const float* __restrict__ Wa,  const float* __restrict__ Wm,
            const float* __restrict__ Wr0, const float* __restrict__ Wr1,
            const float* __restrict__ b0,  const float* __restrict__ b1) {
    const float* hin  = (IO == 0) ? xin : (IO == 1 ? g_h0 : g_h1);
    float*       hout = (IO == 1) ? g_h1 : g_h0;

    int t = threadIdx.x;
    int lane = t & 31;
    int w = t >> 5;

    if (ZERO) {
        for (int i = blockIdx.x * 256 + t; i < N_NODES; i += gridDim.x * 256) {
            g_cnt_tp[i] = 0;
            g_cnt_it[i] = 0;
        }
    }

    // weights into registers: lane owns output channel `lane`
    float wa[CIN], wm[CIN], wr[CIN];
#pragma unroll
    for (int c = 0; c < CIN; c++) {
        wa[c] = Wa[c * 32 + lane];
        wm[c] = Wm[c * 32 + lane];
        wr[c] = Wr0[c * 32 + lane] + Wr1[c * 32 + lane];
    }
    float bcomb = b0[lane] + b1[lane];

    __shared__ __align__(16) float sA[8][32];
    __shared__ __align__(16) float sM[8][32];
    __shared__ __align__(16) float sX[8][32];

    const bool ok = (CIN == 32) || (lane < CIN);
    int gw = blockIdx.x * 8 + w;
    int nw = gridDim.x * 8;

    for (int node = gw; node < N_NODES; node += nw) {
        float X = ok ? hin[node * CIN + lane] : 0.f;

        // ---- add-aggregation over temp_previous ----
        float A0 = 0.f, A1 = 0.f, A2 = 0.f, A3 = 0.f;
        {
            int beg = g_off_tp[node], end = g_off_tp[node + 1];
            for (int j = beg; j < end; ) {
                int s = (j + lane < end) ? g_src_tp[j + lane] : 0;
                int rem = min(32, end - j);
                int k = 0;
                for (; k + 4 <= rem; k += 4) {
                    int s0 = __shfl_sync(0xffffffffu, s, k);
                    int s1 = __shfl_sync(0xffffffffu, s, k + 1);
                    int s2 = __shfl_sync(0xffffffffu, s, k + 2);
                    int s3 = __shfl_sync(0xffffffffu, s, k + 3);
                    if (ok) {
                        A0 += hin[s0 * CIN + lane];
                        A1 += hin[s1 * CIN + lane];
                        A2 += hin[s2 * CIN + lane];
                        A3 += hin[s3 * CIN + lane];
                    }
                }
                for (; k < rem; k++) {
                    int sk = __shfl_sync(0xffffffffu, s, k);
                    if (ok) A0 += hin[sk * CIN + lane];
                }
                j += rem;
            }
        }
        float A = (A0 + A1) + (A2 + A3);

        // ---- mean-aggregation over intersects ----
        float M0 = 0.f, M1 = 0.f, M2 = 0.f, M3 = 0.f;
        int beg = g_off_it[node], end = g_off_it[node + 1];
        int cnt = end - beg;
        for (int j = beg; j < end; ) {
            int s = (j + lane < end) ? g_src_it[j + lane] : 0;
            int rem = min(32, end - j);
            int k = 0;
            for (; k + 4 <= rem; k += 4) {
                int s0 = __shfl_sync(0xffffffffu, s, k);
                int s1 = __shfl_sync(0xffffffffu, s, k + 1);
                int s2 = __shfl_sync(0xffffffffu, s, k + 2);
                int s3 = __shfl_sync(0xffffffffu, s, k + 3);
                if (ok) {
                    M0 += hin[s0 * CIN + lane];
                    M1 += hin[s1 * CIN + lane];
                    M2 += hin[s2 * CIN + lane];
                    M3 += hin[s3 * CIN + lane];
                }
            }
            for (; k < rem; k++) {
                int sk = __shfl_sync(0xffffffffu, s, k);
                if (ok) M0 += hin[sk * CIN + lane];
            }
            j += rem;
        }
        float M = ((M0 + M1) + (M2 + M3)) / fmaxf((float)cnt, 1.0f);

        // ---- transpose A/M/X via smem, epilogue with register weights ----
        __syncwarp();                    // previous iteration's reads done
        sA[w][lane] = A;
        sM[w][lane] = M;
        sX[w][lane] = X;
        __syncwarp();

        float out = bcomb;
        if (CIN == 32) {
#pragma unroll
            for (int c4 = 0; c4 < 8; c4++) {
                float4 a  = *(const float4*)&sA[w][c4 * 4];
                float4 m  = *(const float4*)&sM[w][c4 * 4];
                float4 xx = *(const float4*)&sX[w][c4 * 4];
                out += a.x  * wa[4 * c4 + 0] + a.y  * wa[4 * c4 + 1]
                     + a.z  * wa[4 * c4 + 2] + a.w  * wa[4 * c4 + 3];
                out += m.x  * wm[4 * c4 + 0] + m.y  * wm[4 * c4 + 1]
                     + m.z  * wm[4 * c4 + 2] + m.w  * wm[4 * c4 + 3];
                out += xx.x * wr[4 * c4 + 0] + xx.y * wr[4 * c4 + 1]
                     + xx.z * wr[4 * c4 + 2] + xx.w * wr[4 * c4 + 3];
            }
        } else {
#pragma unroll
            for (int c = 0; c < CIN; c++) {
                out += sA[w][c] * wa[c] + sM[w][c] * wm[c] + sX[w][c] * wr[c];
            }
        }
        if (RES) out += X;
        hout[node * 32 + lane] = fmaxf(out, 0.f);
    }
}

// -------- final linear 32 -> 128 --------
__global__ void __launch_bounds__(256)
out_kernel(float* __restrict__ out,
           const float* __restrict__ Wout, const float* __restrict__ bout) {
    __shared__ __align__(16) float s_w[32 * 128];
    __shared__ __align__(16) float s_b[128];
    int t = threadIdx.x;
    for (int i = t; i < 32 * 128; i += blockDim.x) s_w[i] = Wout[i];
    if (t < 128) s_b[t] = bout[t];
    __syncthreads();

    int lane = t & 31;
    int node = blockIdx.x * (blockDim.x >> 5) + (t >> 5);
    if (node >= N_NODES) return;

    float h = g_h0[node * 32 + lane];
    float4 acc = *(const float4*)&s_b[lane * 4];
#pragma unroll
    for (int c = 0; c < 32; c++) {
        float hv = __shfl_sync(0xffffffffu, h, c);
        float4 w = *(const float4*)&s_w[c * 128 + lane * 4];
        acc.x += hv * w.x; acc.y += hv * w.y;
        acc.z += hv * w.z; acc.w += hv * w.w;
    }
    *(float4*)&out[node * 128 + lane * 4] = acc;
}

extern "C" void kernel_launch(void* const* d_in, const int* in_sizes, int n_in,
                              void* d_out, int out_size) {
    const float* x       = (const float*)d_in[0];
    const int*   ei_tp   = (const int*)d_in[1];    // (2, E_TP) int32
    const int*   ei_it   = (const int*)d_in[2];    // (2, E_IT) int32
    const float* W0_rel  = (const float*)d_in[3];  // (2,6,32)
    const float* W0_root = (const float*)d_in[4];  // (2,6,32)
    const float* b0      = (const float*)d_in[5];  // (2,32)
    const float* W_rel   = (const float*)d_in[6];  // (4,2,32,32)
    const float* W_root  = (const float*)d_in[7];  // (4,2,32,32)
    const float* b       = (const float*)d_in[8];  // (4,2,32)
    const float* Wout    = (const float*)d_in[9];  // (32,128)
    const float* bout    = (const float*)d_in[10]; // (128,)
    float*       out     = (float*)d_out;

    int ge = (E_IT + 255) / 256;
    hist_kernel<<<ge, 256>>>(ei_tp, ei_it);
    scan1_kernel<<<NB, 1024>>>();
    scan23_kernel<<<NB, 1024>>>();
    scatter_kernel<<<ge, 256>>>(ei_tp, ei_it);

    // head: 6 -> 32, no residual, x -> g_h0 ; also re-zeroes counts for the
    // next graph replay (hist_kernel requires zeros).
    conv_kernel<6, false, 0, true><<<CONV_GRID, 256>>>(x,
        W0_rel, W0_rel + 6 * 32, W0_root, W0_root + 6 * 32, b0, b0 + 32);

    // 4 residual blocks, ping-pong g_h0 <-> g_h1
    for (int i = 0; i < 4; i++) {
        const float* wr  = W_rel  + i * 2048;
        const float* wro = W_root + i * 2048;
        const float* bb  = b      + i * 64;
        if ((i & 1) == 0)
            conv_kernel<32, true, 1, false><<<CONV_GRID, 256>>>(nullptr,
                wr, wr + 1024, wro, wro + 1024, bb, bb + 32);
        else
            conv_kernel<32, true, 2, false><<<CONV_GRID, 256>>>(nullptr,
                wr, wr + 1024, wro, wro + 1024, bb, bb + 32);
    }
    // after head->h0, blocks: h0->h1->h0->h1->h0 ; final in g_h0
    int gn = (N_NODES + 7) / 8;
    out_kernel<<<gn, 256>>>(out, Wout, bout);
}

// round 10
// speedup vs baseline: 1.5913x; 1.5913x over previous
#include <cuda_runtime.h>

#define N_NODES 200000
#define E_TP    200000
#define E_IT    3200000
#define NB      ((N_NODES + 1023) / 1024)   // 196 scan blocks

// -------- scratch (static device globals; no allocation) --------
__device__ int   g_cnt_tp[N_NODES];
__device__ int   g_cnt_it[N_NODES];
__device__ int   g_off_tp[N_NODES + 1];
__device__ int   g_off_it[N_NODES + 1];
__device__ int   g_src_tp[E_TP];
__device__ int   g_src_it[E_IT];
__device__ int   g_bsum[2 * 256];
__device__ float g_h [N_NODES * 32];   // current features
__device__ float g_ya[N_NODES * 32];   // h @ Wrel_tp   (gathered with 'add')
__device__ float g_ym[N_NODES * 32];   // h @ Wrel_it   (gathered with 'mean')
__device__ float g_z [N_NODES * 32];   // h @ (Wroot0+Wroot1) + bias (+ res)

// -------- CSR build --------
// counts start at 0 (zero-init at load; re-zeroed by transform0 each replay).
__global__ void hist_kernel(const int* __restrict__ ei_tp,
                            const int* __restrict__ ei_it) {
    int e = blockIdx.x * blockDim.x + threadIdx.x;
    if (e < E_TP) atomicAdd(&g_cnt_tp[ei_tp[E_TP + e]], 1);
    if (e < E_IT) atomicAdd(&g_cnt_it[ei_it[E_IT + e]], 1);
}

// pass 1: per-block sums (1024 elems/block) for both count arrays
__global__ void __launch_bounds__(1024) scan1_kernel() {
    int b = blockIdx.x, t = threadIdx.x;
    int i = b * 1024 + t;
    int vtp = (i < N_NODES) ? g_cnt_tp[i] : 0;
    int vit = (i < N_NODES) ? g_cnt_it[i] : 0;
#pragma unroll
    for (int o = 16; o; o >>= 1) {
        vtp += __shfl_down_sync(0xffffffffu, vtp, o);
        vit += __shfl_down_sync(0xffffffffu, vit, o);
    }
    __shared__ int stp[32], sit[32];
    if ((t & 31) == 0) { stp[t >> 5] = vtp; sit[t >> 5] = vit; }
    __syncthreads();
    if (t < 32) {
        int a = stp[t], c = sit[t];
#pragma unroll
        for (int o = 16; o; o >>= 1) {
            a += __shfl_down_sync(0xffffffffu, a, o);
            c += __shfl_down_sync(0xffffffffu, c, o);
        }
        if (t == 0) { g_bsum[b] = a; g_bsum[256 + b] = c; }
    }
}

// pass 2+3 fused: per-block prefix of block sums + block-local scan.
// Resets g_cnt_* to 0 so scatter can use them as cursors.
__global__ void __launch_bounds__(1024) scan23_kernel() {
    __shared__ int s[1024];
    __shared__ int red0[32], red1[32];
    __shared__ int s_boff[2];
    int b = blockIdx.x, t = threadIdx.x;

    int p0 = (t < b) ? g_bsum[t] : 0;
    int p1 = (t < b) ? g_bsum[256 + t] : 0;
#pragma unroll
    for (int o = 16; o; o >>= 1) {
        p0 += __shfl_down_sync(0xffffffffu, p0, o);
        p1 += __shfl_down_sync(0xffffffffu, p1, o);
    }
    if ((t & 31) == 0) { red0[t >> 5] = p0; red1[t >> 5] = p1; }
    __syncthreads();
    if (t < 32) {
        int a = red0[t], c = red1[t];
#pragma unroll
        for (int o = 16; o; o >>= 1) {
            a += __shfl_down_sync(0xffffffffu, a, o);
            c += __shfl_down_sync(0xffffffffu, c, o);
        }
        if (t == 0) { s_boff[0] = a; s_boff[1] = c; }
    }
    __syncthreads();
    int boff0 = s_boff[0], boff1 = s_boff[1];

    int i = b * 1024 + t;

    int v = (i < N_NODES) ? g_cnt_tp[i] : 0;
    if (i < N_NODES) g_cnt_tp[i] = 0;
    s[t] = v;
    __syncthreads();
    for (int d = 1; d < 1024; d <<= 1) {
        int w = (t >= d) ? s[t - d] : 0;
        __syncthreads();
        s[t] += w;
        __syncthreads();
    }
    if (i < N_NODES) g_off_tp[i] = boff0 + s[t] - v;
    __syncthreads();

    v = (i < N_NODES) ? g_cnt_it[i] : 0;
    if (i < N_NODES) g_cnt_it[i] = 0;
    s[t] = v;
    __syncthreads();
    for (int d = 1; d < 1024; d <<= 1) {
        int w = (t >= d) ? s[t - d] : 0;
        __syncthreads();
        s[t] += w;
        __syncthreads();
    }
    if (i < N_NODES) g_off_it[i] = boff1 + s[t] - v;

    if (b == 0 && t == 0) { g_off_tp[N_NODES] = E_TP; g_off_it[N_NODES] = E_IT; }
}

__global__ void scatter_kernel(const int* __restrict__ ei_tp,
                               const int* __restrict__ ei_it) {
    int e = blockIdx.x * blockDim.x + threadIdx.x;
    if (e < E_TP) {
        int src = ei_tp[e];
        int dst = ei_tp[E_TP + e];
        int pos = g_off_tp[dst] + atomicAdd(&g_cnt_tp[dst], 1);
        g_src_tp[pos] = src;
    }
    if (e < E_IT) {
        int src = ei_it[e];
        int dst = ei_it[E_IT + e];
        int pos = g_off_it[dst] + atomicAdd(&g_cnt_it[dst], 1);
        g_src_it[pos] = src;
    }
}

// -------- per-layer transform: ya/ym/z from h (weights in registers) --------
// Warp per node; lane = output channel. Grid-stride so the register-resident
// weights amortize. HEAD=true reads xin (CIN=6); else reads g_h internally
// (never pass __device__ symbols from host!).
template <int CIN, bool RES, bool HEAD, bool ZERO>
__global__ void __launch_bounds__(128)
transform_kernel(const float* __restrict__ xin,
                 const float* __restrict__ Wa,  const float* __restrict__ Wm,
                 const float* __restrict__ Wr0, const float* __restrict__ Wr1,
                 const float* __restrict__ b0,  const float* __restrict__ b1) {
    const float* hin = HEAD ? xin : (const float*)g_h;

    int t = threadIdx.x;
    int lane = t & 31;
    int w = t >> 5;

    if (ZERO) {  // re-zero counts for the next graph replay's hist_kernel
        for (int i = blockIdx.x * 128 + t; i < N_NODES; i += gridDim.x * 128) {
            g_cnt_tp[i] = 0;
            g_cnt_it[i] = 0;
        }
    }

    float wa[CIN], wm[CIN], wr[CIN];
#pragma unroll
    for (int c = 0; c < CIN; c++) {
        wa[c] = Wa[c * 32 + lane];
        wm[c] = Wm[c * 32 + lane];
        wr[c] = Wr0[c * 32 + lane] + Wr1[c * 32 + lane];
    }
    float bc = b0[lane] + b1[lane];

    __shared__ __align__(16) float sv[4][32];

    int gw = blockIdx.x * 4 + w;
    int nw = gridDim.x * 4;
    for (int node = gw; node < N_NODES; node += nw) {
        float X = (CIN == 32 || lane < CIN) ? hin[node * CIN + lane] : 0.f;
        __syncwarp();
        sv[w][lane] = X;
        __syncwarp();

        float ya = 0.f, ym = 0.f, z = bc;
        if (CIN == 32) {
#pragma unroll
            for (int c4 = 0; c4 < 8; c4++) {
                float4 v = *(const float4*)&sv[w][c4 * 4];
                ya += v.x * wa[4 * c4 + 0] + v.y * wa[4 * c4 + 1]
                    + v.z * wa[4 * c4 + 2] + v.w * wa[4 * c4 + 3];
                ym += v.x * wm[4 * c4 + 0] + v.y * wm[4 * c4 + 1]
                    + v.z * wm[4 * c4 + 2] + v.w * wm[4 * c4 + 3];
                z  += v.x * wr[4 * c4 + 0] + v.y * wr[4 * c4 + 1]
                    + v.z * wr[4 * c4 + 2] + v.w * wr[4 * c4 + 3];
            }
        } else {
#pragma unroll
            for (int c = 0; c < CIN; c++) {
                float v = sv[w][c];
                ya += v * wa[c];
                ym += v * wm[c];
                z  += v * wr[c];
            }
        }
        if (RES) z += X;
        g_ya[node * 32 + lane] = ya;
        g_ym[node * 32 + lane] = ym;
        g_z [node * 32 + lane] = z;
    }
}

// -------- per-layer aggregation: h' = relu(add(ya) + mean(ym) + z) --------
__global__ void __launch_bounds__(256)
aggregate_kernel() {
    int t = threadIdx.x;
    int lane = t & 31;
    int node = blockIdx.x * 8 + (t >> 5);
    if (node >= N_NODES) return;

    float acc = g_z[node * 32 + lane];

    // add-aggregation over temp_previous (mean degree ~1)
    {
        int beg = g_off_tp[node], end = g_off_tp[node + 1];
        for (int j = beg; j < end; ) {
            int s = (j + lane < end) ? g_src_tp[j + lane] : 0;
            int rem = min(32, end - j);
            for (int k = 0; k < rem; k++) {
                int sk = __shfl_sync(0xffffffffu, s, k);
                acc += g_ya[sk * 32 + lane];
            }
            j += rem;
        }
    }

    // mean-aggregation over intersects (mean degree ~16)
    float M0 = 0.f, M1 = 0.f, M2 = 0.f, M3 = 0.f;
    int beg = g_off_it[node], end = g_off_it[node + 1];
    int cnt = end - beg;
    for (int j = beg; j < end; ) {
        int s = (j + lane < end) ? g_src_it[j + lane] : 0;
        int rem = min(32, end - j);
        int k = 0;
        for (; k + 4 <= rem; k += 4) {
            int s0 = __shfl_sync(0xffffffffu, s, k);
            int s1 = __shfl_sync(0xffffffffu, s, k + 1);
            int s2 = __shfl_sync(0xffffffffu, s, k + 2);
            int s3 = __shfl_sync(0xffffffffu, s, k + 3);
            M0 += g_ym[s0 * 32 + lane];
            M1 += g_ym[s1 * 32 + lane];
            M2 += g_ym[s2 * 32 + lane];
            M3 += g_ym[s3 * 32 + lane];
        }
        for (; k < rem; k++) {
            int sk = __shfl_sync(0xffffffffu, s, k);
            M0 += g_ym[sk * 32 + lane];
        }
        j += rem;
    }
    acc += ((M0 + M1) + (M2 + M3)) / fmaxf((float)cnt, 1.0f);

    g_h[node * 32 + lane] = fmaxf(acc, 0.f);
}

// -------- final linear 32 -> 128 --------
__global__ void __launch_bounds__(256)
out_kernel(float* __restrict__ out,
           const float* __restrict__ Wout, const float* __restrict__ bout) {
    __shared__ __align__(16) float s_w[32 * 128];
    __shared__ __align__(16) float s_b[128];
    int t = threadIdx.x;
    for (int i = t; i < 32 * 128; i += blockDim.x) s_w[i] = Wout[i];
    if (t < 128) s_b[t] = bout[t];
    __syncthreads();

    int lane = t & 31;
    int node = blockIdx.x * (blockDim.x >> 5) + (t >> 5);
    if (node >= N_NODES) return;

    float h = g_h[node * 32 + lane];
    float4 acc = *(const float4*)&s_b[lane * 4];
#pragma unroll
    for (int c = 0; c < 32; c++) {
        float hv = __shfl_sync(0xffffffffu, h, c);
        float4 w = *(const float4*)&s_w[c * 128 + lane * 4];
        acc.x += hv * w.x; acc.y += hv * w.y;
        acc.z += hv * w.z; acc.w += hv * w.w;
    }
    *(float4*)&out[node * 128 + lane * 4] = acc;
}

extern "C" void kernel_launch(void* const* d_in, const int* in_sizes, int n_in,
                              void* d_out, int out_size) {
    const float* x       = (const float*)d_in[0];
    const int*   ei_tp   = (const int*)d_in[1];    // (2, E_TP) int32
    const int*   ei_it   = (const int*)d_in[2];    // (2, E_IT) int32
    const float* W0_rel  = (const float*)d_in[3];  // (2,6,32)
    const float* W0_root = (const float*)d_in[4];  // (2,6,32)
    const float* b0      = (const float*)d_in[5];  // (2,32)
    const float* W_rel   = (const float*)d_in[6];  // (4,2,32,32)
    const float* W_root  = (const float*)d_in[7];  // (4,2,32,32)
    const float* b       = (const float*)d_in[8];  // (4,2,32)
    const float* Wout    = (const float*)d_in[9];  // (32,128)
    const float* bout    = (const float*)d_in[10]; // (128,)
    float*       out     = (float*)d_out;

    int ge = (E_IT + 255) / 256;
    hist_kernel<<<ge, 256>>>(ei_tp, ei_it);
    scan1_kernel<<<NB, 1024>>>();
    scan23_kernel<<<NB, 1024>>>();
    scatter_kernel<<<ge, 256>>>(ei_tp, ei_it);

    int gt = 1184;                       // transform grid (8 waves-ish)
    int ga = (N_NODES + 7) / 8;          // aggregate: warp per node

    // head layer: 6 -> 32 (also re-zeroes counts for next replay)
    transform_kernel<6, false, true, true><<<gt, 128>>>(x,
        W0_rel, W0_rel + 6 * 32, W0_root, W0_root + 6 * 32, b0, b0 + 32);
    aggregate_kernel<<<ga, 256>>>();

    // 4 residual blocks 32 -> 32 (in-place on g_h; input selected in-kernel)
    for (int i = 0; i < 4; i++) {
        const float* wr  = W_rel  + i * 2048;
        const float* wro = W_root + i * 2048;
        const float* bb  = b      + i * 64;
        transform_kernel<32, true, false, false><<<gt, 128>>>(nullptr,
            wr, wr + 1024, wro, wro + 1024, bb, bb + 32);
        aggregate_kernel<<<ga, 256>>>();
    }

    out_kernel<<<ga, 256>>>(out, Wout, bout);
}

// round 12
// speedup vs baseline: 1.7756x; 1.1158x over previous
#include <cuda_runtime.h>

#define N_NODES 200000
#define E_TP    200000
#define E_IT    3200000
#define NB      ((N_NODES + 1023) / 1024)   // 196 scan blocks

// -------- scratch (static device globals; no allocation) --------
__device__ int   g_cnt_tp[N_NODES];
__device__ int   g_cnt_it[N_NODES];
__device__ int   g_off_tp[N_NODES + 1];
__device__ int   g_off_it[N_NODES + 1];
__device__ int   g_src_tp[E_TP];
__device__ int   g_src_it[E_IT];
__device__ int   g_bsum[2 * 256];
__device__ __align__(16) float g_h [N_NODES * 32];
__device__ __align__(16) float g_ya[N_NODES * 32];
__device__ __align__(16) float g_ym[N_NODES * 32];
__device__ __align__(16) float g_z [N_NODES * 32];

// -------- CSR build --------
__global__ void hist_kernel(const int* __restrict__ ei_tp,
                            const int* __restrict__ ei_it) {
    int e = blockIdx.x * blockDim.x + threadIdx.x;
    if (e < E_TP) atomicAdd(&g_cnt_tp[ei_tp[E_TP + e]], 1);
    if (e < E_IT) atomicAdd(&g_cnt_it[ei_it[E_IT + e]], 1);
}

__global__ void __launch_bounds__(1024) scan1_kernel() {
    int b = blockIdx.x, t = threadIdx.x;
    int i = b * 1024 + t;
    int vtp = (i < N_NODES) ? g_cnt_tp[i] : 0;
    int vit = (i < N_NODES) ? g_cnt_it[i] : 0;
#pragma unroll
    for (int o = 16; o; o >>= 1) {
        vtp += __shfl_down_sync(0xffffffffu, vtp, o);
        vit += __shfl_down_sync(0xffffffffu, vit, o);
    }
    __shared__ int stp[32], sit[32];
    if ((t & 31) == 0) { stp[t >> 5] = vtp; sit[t >> 5] = vit; }
    __syncthreads();
    if (t < 32) {
        int a = stp[t], c = sit[t];
#pragma unroll
        for (int o = 16; o; o >>= 1) {
            a += __shfl_down_sync(0xffffffffu, a, o);
            c += __shfl_down_sync(0xffffffffu, c, o);
        }
        if (t == 0) { g_bsum[b] = a; g_bsum[256 + b] = c; }
    }
}

__global__ void __launch_bounds__(1024) scan23_kernel() {
    __shared__ int s[1024];
    __shared__ int red0[32], red1[32];
    __shared__ int s_boff[2];
    int b = blockIdx.x, t = threadIdx.x;

    int p0 = (t < b) ? g_bsum[t] : 0;
    int p1 = (t < b) ? g_bsum[256 + t] : 0;
#pragma unroll
    for (int o = 16; o; o >>= 1) {
        p0 += __shfl_down_sync(0xffffffffu, p0, o);
        p1 += __shfl_down_sync(0xffffffffu, p1, o);
    }
    if ((t & 31) == 0) { red0[t >> 5] = p0; red1[t >> 5] = p1; }
    __syncthreads();
    if (t < 32) {
        int a = red0[t], c = red1[t];
#pragma unroll
        for (int o = 16; o; o >>= 1) {
            a += __shfl_down_sync(0xffffffffu, a, o);
            c += __shfl_down_sync(0xffffffffu, c, o);
        }
        if (t == 0) { s_boff[0] = a; s_boff[1] = c; }
    }
    __syncthreads();
    int boff0 = s_boff[0], boff1 = s_boff[1];

    int i = b * 1024 + t;

    int v = (i < N_NODES) ? g_cnt_tp[i] : 0;
    if (i < N_NODES) g_cnt_tp[i] = 0;
    s[t] = v;
    __syncthreads();
    for (int d = 1; d < 1024; d <<= 1) {
        int w = (t >= d) ? s[t - d] : 0;
        __syncthreads();
        s[t] += w;
        __syncthreads();
    }
    if (i < N_NODES) g_off_tp[i] = boff0 + s[t] - v;
    __syncthreads();

    v = (i < N_NODES) ? g_cnt_it[i] : 0;
    if (i < N_NODES) g_cnt_it[i] = 0;
    s[t] = v;
    __syncthreads();
    for (int d = 1; d < 1024; d <<= 1) {
        int w = (t >= d) ? s[t - d] : 0;
        __syncthreads();
        s[t] += w;
        __syncthreads();
    }
    if (i < N_NODES) g_off_it[i] = boff1 + s[t] - v;

    if (b == 0 && t == 0) { g_off_tp[N_NODES] = E_TP; g_off_it[N_NODES] = E_IT; }
}

__global__ void scatter_kernel(const int* __restrict__ ei_tp,
                               const int* __restrict__ ei_it) {
    int e = blockIdx.x * blockDim.x + threadIdx.x;
    if (e < E_TP) {
        int src = ei_tp[e];
        int dst = ei_tp[E_TP + e];
        int pos = g_off_tp[dst] + atomicAdd(&g_cnt_tp[dst], 1);
        g_src_tp[pos] = src;
    }
    if (e < E_IT) {
        int src = ei_it[e];
        int dst = ei_it[E_IT + e];
        int pos = g_off_it[dst] + atomicAdd(&g_cnt_it[dst], 1);
        g_src_it[pos] = src;
    }
}

// -------- per-layer transform: ya/ym/z from h (weights in registers) --------
template <int CIN, bool RES, bool HEAD, bool ZERO>
__global__ void __launch_bounds__(128)
transform_kernel(const float* __restrict__ xin,
                 const float* __restrict__ Wa,  const float* __restrict__ Wm,
                 const float* __restrict__ Wr0, const float* __restrict__ Wr1,
                 const float* __restrict__ b0,  const float* __restrict__ b1) {
    const float* hin = HEAD ? xin : (const float*)g_h;

    int t = threadIdx.x;
    int lane = t & 31;
    int w = t >> 5;

    if (ZERO) {
        for (int i = blockIdx.x * 128 + t; i < N_NODES; i += gridDim.x * 128) {
            g_cnt_tp[i] = 0;
            g_cnt_it[i] = 0;
        }
    }

    float wa[CIN], wm[CIN], wr[CIN];
#pragma unroll
    for (int c = 0; c < CIN; c++) {
        wa[c] = Wa[c * 32 + lane];
        wm[c] = Wm[c * 32 + lane];
        wr[c] = Wr0[c * 32 + lane] + Wr1[c * 32 + lane];
    }
    float bc = b0[lane] + b1[lane];

    __shared__ __align__(16) float sv[4][32];

    int gw = blockIdx.x * 4 + w;
    int nw = gridDim.x * 4;
    for (int node = gw; node < N_NODES; node += nw) {
        float X = (CIN == 32 || lane < CIN) ? hin[node * CIN + lane] : 0.f;
        __syncwarp();
        sv[w][lane] = X;
        __syncwarp();

        float ya = 0.f, ym = 0.f, z = bc;
        if (CIN == 32) {
#pragma unroll
            for (int c4 = 0; c4 < 8; c4++) {
                float4 v = *(const float4*)&sv[w][c4 * 4];
                ya += v.x * wa[4 * c4 + 0] + v.y * wa[4 * c4 + 1]
                    + v.z * wa[4 * c4 + 2] + v.w * wa[4 * c4 + 3];
                ym += v.x * wm[4 * c4 + 0] + v.y * wm[4 * c4 + 1]
                    + v.z * wm[4 * c4 + 2] + v.w * wm[4 * c4 + 3];
                z  += v.x * wr[4 * c4 + 0] + v.y * wr[4 * c4 + 1]
                    + v.z * wr[4 * c4 + 2] + v.w * wr[4 * c4 + 3];
            }
        } else {
#pragma unroll
            for (int c = 0; c < CIN; c++) {
                float v = sv[w][c];
                ya += v * wa[c];
                ym += v * wm[c];
                z  += v * wr[c];
            }
        }
        if (RES) z += X;
        g_ya[node * 32 + lane] = ya;
        g_ym[node * 32 + lane] = ym;
        g_z [node * 32 + lane] = z;
    }
}

// -------- per-layer aggregation: h' = relu(add(ya) + mean(ym) + z) --------
// 4 nodes per warp; 8-lane subgroup per node; lane covers 4 channels (float4).
// Gathers are LDG.128: 4x fewer load instructions than the scalar version.
__global__ void __launch_bounds__(256)
aggregate_kernel() {
    int t = threadIdx.x;
    int lane = t & 31;
    int g = lane >> 3;            // subgroup (node) index within warp: 0..3
    int k = lane & 7;             // float4 slot: channels [4k, 4k+4)
    unsigned gmask = 0xFFu << (g * 8);

    int node = (blockIdx.x * 8 + (t >> 5)) * 4 + g;
    if (node >= N_NODES) return;

    const float4* ya4 = (const float4*)g_ya;
    const float4* ym4 = (const float4*)g_ym;

    float4 acc = *(const float4*)&g_z[node * 32 + k * 4];

    // add-aggregation over temp_previous (mean degree ~1)
    {
        int beg = g_off_tp[node], end = g_off_tp[node + 1];
        for (int j = beg; j < end; ) {
            int idx = (j + k < end) ? g_src_tp[j + k] : 0;
            int rem = min(8, end - j);
            for (int kk = 0; kk < rem; kk++) {
                int s = __shfl_sync(gmask, idx, g * 8 + kk);
                float4 v = ya4[s * 8 + k];
                acc.x += v.x; acc.y += v.y; acc.z += v.z; acc.w += v.w;
            }
            j += rem;
        }
    }

    // mean-aggregation over intersects (mean degree ~16)
    float4 m0 = {0.f, 0.f, 0.f, 0.f}, m1 = {0.f, 0.f, 0.f, 0.f};
    float4 m2 = {0.f, 0.f, 0.f, 0.f}, m3 = {0.f, 0.f, 0.f, 0.f};
    int beg = g_off_it[node], end = g_off_it[node + 1];
    int cnt = end - beg;
    for (int j = beg; j < end; ) {
        int idx = (j + k < end) ? g_src_it[j + k] : 0;
        int rem = min(8, end - j);
        int kk = 0;
        for (; kk + 4 <= rem; kk += 4) {
            int s0 = __shfl_sync(gmask, idx, g * 8 + kk);
            int s1 = __shfl_sync(gmask, idx, g * 8 + kk + 1);
            int s2 = __shfl_sync(gmask, idx, g * 8 + kk + 2);
            int s3 = __shfl_sync(gmask, idx, g * 8 + kk + 3);
            float4 v0 = ym4[s0 * 8 + k];
            float4 v1 = ym4[s1 * 8 + k];
            float4 v2 = ym4[s2 * 8 + k];
            float4 v3 = ym4[s3 * 8 + k];
            m0.x += v0.x; m0.y += v0.y; m0.z += v0.z; m0.w += v0.w;
            m1.x += v1.x; m1.y += v1.y; m1.z += v1.z; m1.w += v1.w;
            m2.x += v2.x; m2.y += v2.y; m2.z += v2.z; m2.w += v2.w;
            m3.x += v3.x; m3.y += v3.y; m3.z += v3.z; m3.w += v3.w;
        }
        for (; kk < rem; kk++) {
            int s = __shfl_sync(gmask, idx, g * 8 + kk);
            float4 v = ym4[s * 8 + k];
            m0.x += v.x; m0.y += v.y; m0.z += v.z; m0.w += v.w;
        }
        j += rem;
    }
    float inv = 1.0f / fmaxf((float)cnt, 1.0f);
    acc.x += ((m0.x + m1.x) + (m2.x + m3.x)) * inv;
    acc.y += ((m0.y + m1.y) + (m2.y + m3.y)) * inv;
    acc.z += ((m0.z + m1.z) + (m2.z + m3.z)) * inv;
    acc.w += ((m0.w + m1.w) + (m2.w + m3.w)) * inv;

    acc.x = fmaxf(acc.x, 0.f);
    acc.y = fmaxf(acc.y, 0.f);
    acc.z = fmaxf(acc.z, 0.f);
    acc.w = fmaxf(acc.w, 0.f);
    *(float4*)&g_h[node * 32 + k * 4] = acc;
}

// -------- final linear 32 -> 128 --------
__global__ void __launch_bounds__(256)
out_kernel(float* __restrict__ out,
           const float* __restrict__ Wout, const float* __restrict__ bout) {
    __shared__ __align__(16) float s_w[32 * 128];
    __shared__ __align__(16) float s_b[128];
    int t = threadIdx.x;
    for (int i = t; i < 32 * 128; i += blockDim.x) s_w[i] = Wout[i];
    if (t < 128) s_b[t] = bout[t];
    __syncthreads();

    int lane = t & 31;
    int node = blockIdx.x * (blockDim.x >> 5) + (t >> 5);
    if (node >= N_NODES) return;

    float h = g_h[node * 32 + lane];
    float4 acc = *(const float4*)&s_b[lane * 4];
#pragma unroll
    for (int c = 0; c < 32; c++) {
        float hv = __shfl_sync(0xffffffffu, h, c);
        float4 w = *(const float4*)&s_w[c * 128 + lane * 4];
        acc.x += hv * w.x; acc.y += hv * w.y;
        acc.z += hv * w.z; acc.w += hv * w.w;
    }
    *(float4*)&out[node * 128 + lane * 4] = acc;
}

extern "C" void kernel_launch(void* const* d_in, const int* in_sizes, int n_in,
                              void* d_out, int out_size) {
    const float* x       = (const float*)d_in[0];
    const int*   ei_tp   = (const int*)d_in[1];    // (2, E_TP) int32
    const int*   ei_it   = (const int*)d_in[2];    // (2, E_IT) int32
    const float* W0_rel  = (const float*)d_in[3];  // (2,6,32)
    const float* W0_root = (const float*)d_in[4];  // (2,6,32)
    const float* b0      = (const float*)d_in[5];  // (2,32)
    const float* W_rel   = (const float*)d_in[6];  // (4,2,32,32)
    const float* W_root  = (const float*)d_in[7];  // (4,2,32,32)
    const float* b       = (const float*)d_in[8];  // (4,2,32)
    const float* Wout    = (const float*)d_in[9];  // (32,128)
    const float* bout    = (const float*)d_in[10]; // (128,)
    float*       out     = (float*)d_out;

    int ge = (E_IT + 255) / 256;
    hist_kernel<<<ge, 256>>>(ei_tp, ei_it);
    scan1_kernel<<<NB, 1024>>>();
    scan23_kernel<<<NB, 1024>>>();
    scatter_kernel<<<ge, 256>>>(ei_tp, ei_it);

    int gt = 1184;                        // transform grid
    int ga = (N_NODES + 31) / 32;         // aggregate: 32 nodes per block
    int gn = (N_NODES + 7) / 8;           // out: warp per node

    transform_kernel<6, false, true, true><<<gt, 128>>>(x,
        W0_rel, W0_rel + 6 * 32, W0_root, W0_root + 6 * 32, b0, b0 + 32);
    aggregate_kernel<<<ga, 256>>>();

    for (int i = 0; i < 4; i++) {
        const float* wr  = W_rel  + i * 2048;
        const float* wro = W_root + i * 2048;
        const float* bb  = b      + i * 64;
        transform_kernel<32, true, false, false><<<gt, 128>>>(nullptr,
            wr, wr + 1024, wro, wro + 1024, bb, bb + 32);
        aggregate_kernel<<<ga, 256>>>();
    }

    out_kernel<<<gn, 256>>>(out, Wout, bout);
}